// round 10
// baseline (speedup 1.0000x reference)
#include <cuda_runtime.h>
#include <cuda_bf16.h>

#define OUT_SZ 7
#define NCELL (OUT_SZ * OUT_SZ)      // 49
#define NCH 256
#define NQ (NCH / 4)                 // 64 float4 per channel row
#define NTHREADS (NQ * OUT_SZ)       // 448: slot=row i, 64 channel quads

// level thresholds on wh = roi_h*roi_w:
//   level >= c  <=>  wh >= 224^2 * 2^(2*(c-4)),  c = 2.5, 3.5, 4.5
#define T3 6272.0f      // 224^2 / 8
#define T4 25088.0f     // 224^2 / 2
#define T5 100352.0f    // 224^2 * 2

__device__ __forceinline__ float4 lerp2d4(float4 tl, float4 tr, float4 bl, float4 br,
                                          float lx, float ly)
{
    float4 top, bot, v;
    top.x = fmaf(tr.x - tl.x, lx, tl.x);
    top.y = fmaf(tr.y - tl.y, lx, tl.y);
    top.z = fmaf(tr.z - tl.z, lx, tl.z);
    top.w = fmaf(tr.w - tl.w, lx, tl.w);
    bot.x = fmaf(br.x - bl.x, lx, bl.x);
    bot.y = fmaf(br.y - bl.y, lx, bl.y);
    bot.z = fmaf(br.z - bl.z, lx, bl.z);
    bot.w = fmaf(br.w - bl.w, lx, bl.w);
    v.x = fmaf(bot.x - top.x, ly, top.x);
    v.y = fmaf(bot.y - top.y, ly, top.y);
    v.z = fmaf(bot.z - top.z, ly, top.z);
    v.w = fmaf(bot.w - top.w, ly, top.w);
    return v;
}

__global__ __launch_bounds__(NTHREADS, 3)
void roialign_kernel(const float* __restrict__ p2,
                     const float* __restrict__ p3,
                     const float* __restrict__ p4,
                     const float* __restrict__ p5,
                     const float* __restrict__ rois,
                     float* __restrict__ out)
{
    int roi = blockIdx.x;
    int tid = threadIdx.x;
    int cq  = tid & (NQ - 1);        // channel quad 0..63
    int i   = tid >> 6;              // output row 0..6

    // ---- cheap per-thread ROI decode (no MUFU), amortized over 7 cells ----
    const float* r = rois + (size_t)roi * 5;   // [batch, x1, y1, x2, y2]
    float bf  = __ldg(r + 0);
    float rx1 = __ldg(r + 1), ry1 = __ldg(r + 2);
    float rx2 = __ldg(r + 3), ry2 = __ldg(r + 4);
    int b = (int)bf;

    float dx = rx2 - rx1;            // roi_w
    float dy = ry2 - ry1;            // roi_h
    float wh = dy * dx;
    int level = 2 + (wh >= T3) + (wh >= T4) + (wh >= T5);

    const float* fm = level < 4 ? (level == 2 ? p2 : p3)
                                : (level == 4 ? p4 : p5);
    // c = (H-1) * 2^-level, selected per level
    float c = level < 4 ? (level == 2 ? 63.75f   : 15.875f)
                        : (level == 4 ? 3.9375f  : 0.96875f);
    float c6 = c * (1.0f / 6.0f);
    int   Hm1i = (1024 >> level) - 1;
    float Hm1  = (float)Hm1i;
    int   rowstride = 65536 >> level;          // H * NQ (float4 units)

    // crop_and_resize reads boxes as [y1,x1,y2,x2]; roi_align passes
    // [x1,y1,x2,y2]*(1/stride). So the crop's y-axis uses rx, x-axis uses ry.
    float y_base  = rx1 * c;
    float x_base  = ry1 * c;
    float h_scale = dx * c6;
    float w_scale = dy * c6;

    const float4* fm_b = (const float4*)(fm + ((size_t)b << (28 - 2 * level)));
    float4* out_row = (float4*)(out + (size_t)roi * NCELL * NCH)
                      + i * OUT_SZ * NQ + cq;

    // ---- y-axis (hoisted: shared by the whole output row) ----
    float in_y = fmaf((float)i, h_scale, y_base);
    bool  vy   = (in_y >= 0.0f) & (in_y <= Hm1);
    float4 zero = make_float4(0.f, 0.f, 0.f, 0.f);

    if (!vy) {
#pragma unroll
        for (int j = 0; j < OUT_SZ; j++)
            out_row[j * NQ] = zero;
        return;
    }

    float fy = floorf(in_y);
    float ly = in_y - fy;
    int   y0 = (int)fy;                               // valid ⇒ in [0, Hm1i]
    int   yc = (int)fminf(ceilf(in_y), Hm1);
    const float4* r0 = fm_b + y0 * rowstride;
    const float4* r1 = fm_b + yc * rowstride;

    // ---- columns in pairs: issue all 8 loads before the lerps ----
#pragma unroll
    for (int jp = 0; jp < OUT_SZ; jp += 2) {
        const bool hasB = (jp + 1 < OUT_SZ);          // compile-time per copy

        float in_xA = fmaf((float)jp, w_scale, x_base);
        bool  vxA   = (in_xA >= 0.0f) & (in_xA <= Hm1);
        float fxA   = floorf(in_xA);
        float lxA   = in_xA - fxA;
        int x0A = min(max((int)fxA, 0), Hm1i);
        int xcA = (int)fminf(fmaxf(ceilf(in_xA), 0.0f), Hm1);

        float in_xB = fmaf((float)(jp + 1), w_scale, x_base);
        bool  vxB   = hasB & (in_xB >= 0.0f) & (in_xB <= Hm1);
        float fxB   = floorf(in_xB);
        float lxB   = in_xB - fxB;
        int x0B = min(max((int)fxB, 0), Hm1i);
        int xcB = (int)fminf(fmaxf(ceilf(in_xB), 0.0f), Hm1);

        // all 8 loads up front (addresses clamped => always safe)
        float4 a_tl = __ldg(r0 + x0A * NQ + cq);
        float4 a_tr = __ldg(r0 + xcA * NQ + cq);
        float4 a_bl = __ldg(r1 + x0A * NQ + cq);
        float4 a_br = __ldg(r1 + xcA * NQ + cq);
        float4 b_tl, b_tr, b_bl, b_br;
        if (hasB) {
            b_tl = __ldg(r0 + x0B * NQ + cq);
            b_tr = __ldg(r0 + xcB * NQ + cq);
            b_bl = __ldg(r1 + x0B * NQ + cq);
            b_br = __ldg(r1 + xcB * NQ + cq);
        }

        float4 vA = vxA ? lerp2d4(a_tl, a_tr, a_bl, a_br, lxA, ly) : zero;
        out_row[jp * NQ] = vA;

        if (hasB) {
            float4 vB = vxB ? lerp2d4(b_tl, b_tr, b_bl, b_br, lxB, ly) : zero;
            out_row[(jp + 1) * NQ] = vB;
        }
    }
}

extern "C" void kernel_launch(void* const* d_in, const int* in_sizes, int n_in,
                              void* d_out, int out_size)
{
    const float* p2   = (const float*)d_in[0];
    const float* p3   = (const float*)d_in[1];
    const float* p4   = (const float*)d_in[2];
    const float* p5   = (const float*)d_in[3];
    const float* rois = (const float*)d_in[4];
    float* out = (float*)d_out;
    int n_rois = in_sizes[4] / 5;

    roialign_kernel<<<n_rois, NTHREADS>>>(p2, p3, p4, p5, rois, out);
}